// round 12
// baseline (speedup 1.0000x reference)
#include <cuda_runtime.h>
#include <cuda_bf16.h>
#include <cstdint>

// ---------------- problem constants ----------------
#define MROWS 8192          // B*D = 256*32
#define KDIM  1024
#define NCOLS 1024
#define NSTEPS 6
#define NODE_SZ (1024 * 1024)

// ---------------- column split: HMMA vs FFMA ----------------
#define NH_TILES 10          // 10 x 64 = 640 cols via bf16x3 HMMA
#define NF_TILES 3           // 3 x 128 = 384 cols via fp32 FFMA
#define NH_COLS  640

// ---------------- scratch (__device__ globals; no allocation) ----------------
__device__ __nv_bfloat16 g_ah[2][MROWS * KDIM];      // activation hi (ping/pong)
__device__ __nv_bfloat16 g_al[2][MROWS * KDIM];      // activation lo
__device__ float         g_af[2][MROWS * KDIM];      // activation fp32
__device__ __nv_bfloat16 g_wh[NSTEPS][NODE_SZ];      // Wt hi: [n][k]
__device__ __nv_bfloat16 g_wl[NSTEPS][NODE_SZ];      // Wt lo
__device__ float         g_wf[NSTEPS][NODE_SZ];      // Wt fp32

// ---------------- HMMA tiling: 128 x 64, BK=32, 2 stages ----------------
#define NKTH 32
#define ROW_B   48
#define ABLK_B  (128 * ROW_B)          // 6144
#define AREG_B  (4 * ABLK_B)           // 24576
#define BBLK_B  (64 * ROW_B)           // 3072
#define BREG_B  (4 * BBLK_B)           // 12288
#define STAGE_B (AREG_B + BREG_B)      // 36864
#define SMEM_BYTES (2 * STAGE_B)       // 73728  (FFMA path reuses 33792 of it)

// ---------------- FFMA tiling: 128 x 128, BK=16, double buffer ----------------
#define NKTF 64
#define FPAD 132                        // 128 + 4 floats row pad

__device__ __forceinline__ uint32_t s2u(const void* p) {
    uint32_t a;
    asm("{ .reg .u64 t; cvta.to.shared.u64 t, %1; cvt.u32.u64 %0, t; }" : "=r"(a) : "l"(p));
    return a;
}
__device__ __forceinline__ void ldm4(uint32_t* r, uint32_t a) {
    asm volatile("ldmatrix.sync.aligned.m8n8.x4.shared.b16 {%0,%1,%2,%3}, [%4];"
                 : "=r"(r[0]), "=r"(r[1]), "=r"(r[2]), "=r"(r[3]) : "r"(a));
}
__device__ __forceinline__ void mma_bf16(float* d, const uint32_t* a, const uint32_t* b) {
    asm volatile("mma.sync.aligned.m16n8k16.row.col.f32.bf16.bf16.f32 "
                 "{%0,%1,%2,%3}, {%4,%5,%6,%7}, {%8,%9}, {%0,%1,%2,%3};"
                 : "+f"(d[0]), "+f"(d[1]), "+f"(d[2]), "+f"(d[3])
                 : "r"(a[0]), "r"(a[1]), "r"(a[2]), "r"(a[3]), "r"(b[0]), "r"(b[1]));
}
__device__ __forceinline__ void split_bf16(float v, __nv_bfloat16& h, __nv_bfloat16& l) {
    h = __float2bfloat16(v);
    l = __float2bfloat16(v - __bfloat162float(h));
}

// ---------------- prep kernels ----------------
// A0[(b,f)][k=j*32+i] = X[b,i,j,f] in fp32 + bf16 hi/lo.
__global__ void prep_x(const float* __restrict__ X) {
    __shared__ float t[32][33];
    const int b = blockIdx.x >> 5, j = blockIdx.x & 31;
    const int x = threadIdx.x, y = threadIdx.y;
    t[y][x] = X[b * 32768 + y * 1024 + j * 32 + x];   // y=i, x=f (coalesced)
    __syncthreads();
    const float v = t[x][y];                          // x=i, y=f
    __nv_bfloat16 h, l;
    split_bf16(v, h, l);
    const int addr = (b * 32 + y) * 1024 + j * 32 + x;
    g_af[0][addr] = v;
    g_ah[0][addr] = h;
    g_al[0][addr] = l;
}
// Wt[s][n][k] = W[s][(k&31)*32 + (k>>5)][n] in fp32 + bf16 hi/lo.
__global__ void prep_w(const float* __restrict__ W) {
    __shared__ float t[32][33];
    const int s = blockIdx.z;
    const int k0 = blockIdx.x * 32, n0 = blockIdx.y * 32;
    const int x = threadIdx.x, y = threadIdx.y;
    const int kp = k0 + y;
    const int wrow = (kp & 31) * 32 + (kp >> 5);
    t[y][x] = W[s * NODE_SZ + wrow * 1024 + n0 + x];
    __syncthreads();
    const float v = t[x][y];
    __nv_bfloat16 h, l;
    split_bf16(v, h, l);
    const int addr = (n0 + y) * 1024 + k0 + x;
    g_wf[s][addr] = v;
    g_wh[s][addr] = h;
    g_wl[s][addr] = l;
}

// ---------------- combined hybrid kernel ----------------
// blockIdx.x <  NH_TILES : HMMA CTA (bf16 hh+hl+lh), cols blockIdx.x*64 .. +63
// blockIdx.x >= NH_TILES : FFMA CTA (fp32),         cols 640 + (x-NH)*128 .. +127
template <bool EPI>
__global__ __launch_bounds__(256, 2)
void entangler_hybrid(int src, int dst, int s,
                      const float* __restrict__ bias, float* __restrict__ out) {
    extern __shared__ char smem[];
    const int tid  = threadIdx.x;
    const int row0 = blockIdx.y * 128;

    // ---- shared epilogue writer: scatter into next stage's A (all formats) ----
    __nv_bfloat16* __restrict__ Ahd = g_ah[dst];
    __nv_bfloat16* __restrict__ Ald = g_al[dst];
    float*         __restrict__ Afd = g_af[dst];

    if (blockIdx.x < NH_TILES) {
        // ================= HMMA path: 128 x 64, bf16x3 =================
        const uint32_t smem_u = s2u(smem);
        const int wid  = tid >> 5;
        const int lane = tid & 31;
        const int col0 = blockIdx.x * 64;
        const int warp_m = (wid & 3) * 32;
        const int warp_n = (wid >> 2) * 32;

        const __nv_bfloat16* __restrict__ Ahi = g_ah[src];
        const __nv_bfloat16* __restrict__ Alo = g_al[src];
        const __nv_bfloat16* __restrict__ Whi = g_wh[s];
        const __nv_bfloat16* __restrict__ Wlo = g_wl[s];

        float acc[2][4][4];
#pragma unroll
        for (int mt = 0; mt < 2; mt++)
#pragma unroll
            for (int nt = 0; nt < 4; nt++)
#pragma unroll
                for (int q = 0; q < 4; q++) acc[mt][nt][q] = 0.0f;

        auto issue = [&](int kt, int stg) {
            const uint32_t sbase = smem_u + stg * STAGE_B;
#pragma unroll
            for (int t = 0; t < 4; t++) {            // A: 1024 chunks
                const int idx  = tid + t * 256;
                const int m_l  = idx >> 3;
                const int sub  = idx & 7;
                const int hl   = sub >> 2;
                const int ch   = sub & 3;
                const int ks   = ch >> 1;
                const int half = ch & 1;
                const uint32_t soff = ((hl * 2 + ks) * 128 + m_l) * ROW_B + half * 16;
                const __nv_bfloat16* ga =
                    (hl ? Alo : Ahi) + (row0 + m_l) * 1024 + kt * 32 + ch * 8;
                asm volatile("cp.async.cg.shared.global [%0], [%1], 16;"
                             :: "r"(sbase + soff), "l"(ga));
            }
#pragma unroll
            for (int t = 0; t < 2; t++) {            // B: 512 chunks
                const int idx  = tid + t * 256;
                const int n_l  = idx >> 3;
                const int sub  = idx & 7;
                const int hl   = sub >> 2;
                const int ch   = sub & 3;
                const int ks   = ch >> 1;
                const int half = ch & 1;
                const uint32_t soff = AREG_B + ((hl * 2 + ks) * 64 + n_l) * ROW_B + half * 16;
                const __nv_bfloat16* gb =
                    (hl ? Wlo : Whi) + (col0 + n_l) * 1024 + kt * 32 + ch * 8;
                asm volatile("cp.async.cg.shared.global [%0], [%1], 16;"
                             :: "r"(sbase + soff), "l"(gb));
            }
            asm volatile("cp.async.commit_group;" ::: "memory");
        };

        const int a_lr = (lane & 7) + ((lane >> 3) & 1) * 8;
        const int a_lb = (lane >> 4) * 16;
        const int b_nr = (lane >> 4) * 8 + (lane & 7);
        const int b_lb = ((lane >> 3) & 1) * 16;

        auto compute = [&](int stg) {
            const uint32_t sbase = smem_u + stg * STAGE_B;
#pragma unroll
            for (int ks = 0; ks < 2; ks++) {
                uint32_t ah[2][4], al[2][4], bh[4][2], bl[4][2];
#pragma unroll
                for (int mt = 0; mt < 2; mt++) {
                    const uint32_t ra = (warp_m + mt * 16 + a_lr) * ROW_B + a_lb;
                    ldm4(ah[mt], sbase + (0 + ks) * ABLK_B + ra);
                    ldm4(al[mt], sbase + (2 + ks) * ABLK_B + ra);
                }
#pragma unroll
                for (int ntp = 0; ntp < 2; ntp++) {
                    const uint32_t rb = (warp_n + ntp * 16 + b_nr) * ROW_B + b_lb;
                    uint32_t tmp[4];
                    ldm4(tmp, sbase + AREG_B + (0 + ks) * BBLK_B + rb);
                    bh[2 * ntp][0] = tmp[0]; bh[2 * ntp][1] = tmp[1];
                    bh[2 * ntp + 1][0] = tmp[2]; bh[2 * ntp + 1][1] = tmp[3];
                    ldm4(tmp, sbase + AREG_B + (2 + ks) * BBLK_B + rb);
                    bl[2 * ntp][0] = tmp[0]; bl[2 * ntp][1] = tmp[1];
                    bl[2 * ntp + 1][0] = tmp[2]; bl[2 * ntp + 1][1] = tmp[3];
                }
#pragma unroll
                for (int mt = 0; mt < 2; mt++)
#pragma unroll
                    for (int nt = 0; nt < 4; nt++)
                        mma_bf16(acc[mt][nt], ah[mt], bh[nt]);
#pragma unroll
                for (int mt = 0; mt < 2; mt++)
#pragma unroll
                    for (int nt = 0; nt < 4; nt++)
                        mma_bf16(acc[mt][nt], ah[mt], bl[nt]);
#pragma unroll
                for (int mt = 0; mt < 2; mt++)
#pragma unroll
                    for (int nt = 0; nt < 4; nt++)
                        mma_bf16(acc[mt][nt], al[mt], bh[nt]);
            }
        };

        issue(0, 0);
#pragma unroll 1
        for (int kt = 0; kt < NKTH; kt++) {
            if (kt + 1 < NKTH) {
                issue(kt + 1, (kt + 1) & 1);
                asm volatile("cp.async.wait_group 1;" ::: "memory");
            } else {
                asm volatile("cp.async.wait_group 0;" ::: "memory");
            }
            __syncthreads();
            compute(kt & 1);
            __syncthreads();
        }

        const int lrow = lane >> 2;
        const int lcol = (lane & 3) * 2;
#pragma unroll
        for (int mt = 0; mt < 2; mt++)
#pragma unroll
            for (int nt = 0; nt < 4; nt++) {
                const int gr0 = row0 + warp_m + mt * 16 + lrow;
                const int gn  = col0 + warp_n + nt * 8 + lcol;
#pragma unroll
                for (int half = 0; half < 2; half++) {
                    const int r = gr0 + half * 8;
                    float v0 = acc[mt][nt][half * 2 + 0];
                    float v1 = acc[mt][nt][half * 2 + 1];
                    if (EPI) {
                        const int f = r & 31;
                        v0 = fmaxf(v0 + bias[f * 1024 + gn], 0.0f);
                        v1 = fmaxf(v1 + bias[f * 1024 + gn + 1], 0.0f);
                        *(float2*)(out + r * 1024 + gn) = make_float2(v0, v1);
                    } else {
                        const int b = r >> 5, f = r & 31;
                        const int addr = (b * 32 + (gn >> 5)) * 1024 + f * 32 + (gn & 31);
                        *(float2*)(&Afd[addr]) = make_float2(v0, v1);
                        __nv_bfloat16 h0, l0, h1, l1;
                        split_bf16(v0, h0, l0);
                        split_bf16(v1, h1, l1);
                        __nv_bfloat162 hp; hp.x = h0; hp.y = h1;
                        __nv_bfloat162 lp; lp.x = l0; lp.y = l1;
                        *(__nv_bfloat162*)(&Ahd[addr]) = hp;
                        *(__nv_bfloat162*)(&Ald[addr]) = lp;
                    }
                }
            }
    } else {
        // ================= FFMA path: 128 x 128 fp32 =================
        float (*As)[16][FPAD] = (float (*)[16][FPAD])(smem);
        float (*Bs)[16][FPAD] = (float (*)[16][FPAD])(smem + 2 * 16 * FPAD * 4);

        const int col0 = NH_COLS + (blockIdx.x - NH_TILES) * 128;
        const float* __restrict__ A = g_af[src];
        const float* __restrict__ B = g_wf[s];

        const int tcol = tid & 15;
        const int trow = tid >> 4;
        const int r = tid >> 1, h = tid & 1;
        const float* pA = A + (row0 + r) * 1024 + h * 8;
        const float* pB = B + (col0 + r) * 1024 + h * 8;

        float4 ar0, ar1, br0, br1;
        auto load_g = [&](int kt) {
            const float* a = pA + kt * 16;
            const float* b = pB + kt * 16;
            ar0 = *(const float4*)(a);     ar1 = *(const float4*)(a + 4);
            br0 = *(const float4*)(b);     br1 = *(const float4*)(b + 4);
        };
        auto store_s = [&](int buf) {
            const float av[8] = {ar0.x, ar0.y, ar0.z, ar0.w, ar1.x, ar1.y, ar1.z, ar1.w};
            const float bv[8] = {br0.x, br0.y, br0.z, br0.w, br1.x, br1.y, br1.z, br1.w};
#pragma unroll
            for (int u = 0; u < 8; u++) {
                As[buf][h * 8 + u][r] = av[u];
                Bs[buf][h * 8 + u][r] = bv[u];
            }
        };

        float acc[8][8];
#pragma unroll
        for (int i = 0; i < 8; i++)
#pragma unroll
            for (int j = 0; j < 8; j++) acc[i][j] = 0.0f;

        load_g(0);
        store_s(0);
        __syncthreads();
#pragma unroll 1
        for (int kt = 0; kt < NKTF; kt++) {
            const int cur = kt & 1;
            if (kt + 1 < NKTF) load_g(kt + 1);
#pragma unroll
            for (int kk = 0; kk < 16; kk++) {
                float4 a0 = *(const float4*)&As[cur][kk][trow * 4];
                float4 a1 = *(const float4*)&As[cur][kk][64 + trow * 4];
                float4 b0 = *(const float4*)&Bs[cur][kk][tcol * 4];
                float4 b1 = *(const float4*)&Bs[cur][kk][64 + tcol * 4];
                const float af[8] = {a0.x, a0.y, a0.z, a0.w, a1.x, a1.y, a1.z, a1.w};
                const float bf[8] = {b0.x, b0.y, b0.z, b0.w, b1.x, b1.y, b1.z, b1.w};
#pragma unroll
                for (int i = 0; i < 8; i++)
#pragma unroll
                    for (int j = 0; j < 8; j++)
                        acc[i][j] = fmaf(af[i], bf[j], acc[i][j]);
            }
            if (kt + 1 < NKTF) {
                __syncthreads();
                store_s(cur ^ 1);
                __syncthreads();
            }
        }

#pragma unroll
        for (int u = 0; u < 8; u++) {
            const int rr   = (u < 4) ? (trow * 4 + u) : (64 + trow * 4 + (u - 4));
            const int grow = row0 + rr;
            const int b = grow >> 5, f = grow & 31;
#pragma unroll
            for (int hh = 0; hh < 2; hh++) {
                const int c    = (hh == 0) ? (tcol * 4) : (64 + tcol * 4);
                const int gcol = col0 + c;
                float v[4] = {acc[u][hh * 4 + 0], acc[u][hh * 4 + 1],
                              acc[u][hh * 4 + 2], acc[u][hh * 4 + 3]};
                if (EPI) {
                    const float* bp = bias + f * 1024 + gcol;
                    float4 o = make_float4(fmaxf(v[0] + bp[0], 0.0f),
                                           fmaxf(v[1] + bp[1], 0.0f),
                                           fmaxf(v[2] + bp[2], 0.0f),
                                           fmaxf(v[3] + bp[3], 0.0f));
                    *(float4*)(out + grow * 1024 + gcol) = o;
                } else {
                    const int addr = (b * 32 + (gcol >> 5)) * 1024 + f * 32 + (gcol & 31);
                    *(float4*)(&Afd[addr]) = make_float4(v[0], v[1], v[2], v[3]);
#pragma unroll
                    for (int p = 0; p < 2; p++) {
                        __nv_bfloat16 h0, l0, h1, l1;
                        split_bf16(v[2 * p + 0], h0, l0);
                        split_bf16(v[2 * p + 1], h1, l1);
                        __nv_bfloat162 hp; hp.x = h0; hp.y = h1;
                        __nv_bfloat162 lp; lp.x = l0; lp.y = l1;
                        *(__nv_bfloat162*)(&Ahd[addr + 2 * p]) = hp;
                        *(__nv_bfloat162*)(&Ald[addr + 2 * p]) = lp;
                    }
                }
            }
        }
    }
}

// ---------------- launch ----------------
extern "C" void kernel_launch(void* const* d_in, const int* in_sizes, int n_in,
                              void* d_out, int out_size) {
    const float* X     = (const float*)d_in[0];
    const float* nodes = (const float*)d_in[1];
    const float* bias  = (const float*)d_in[2];
    float* out = (float*)d_out;

    cudaFuncSetAttribute(entangler_hybrid<false>,
                         cudaFuncAttributeMaxDynamicSharedMemorySize, SMEM_BYTES);
    cudaFuncSetAttribute(entangler_hybrid<true>,
                         cudaFuncAttributeMaxDynamicSharedMemorySize, SMEM_BYTES);

    prep_x<<<MROWS, dim3(32, 32)>>>(X);
    prep_w<<<dim3(32, 32, NSTEPS), dim3(32, 32)>>>(nodes);

    dim3 grid(NH_TILES + NF_TILES, MROWS / 128);   // (13, 64)
    entangler_hybrid<false><<<grid, 256, SMEM_BYTES>>>(0, 1, 0, bias, nullptr);
    entangler_hybrid<false><<<grid, 256, SMEM_BYTES>>>(1, 0, 1, bias, nullptr);
    entangler_hybrid<false><<<grid, 256, SMEM_BYTES>>>(0, 1, 2, bias, nullptr);
    entangler_hybrid<false><<<grid, 256, SMEM_BYTES>>>(1, 0, 3, bias, nullptr);
    entangler_hybrid<false><<<grid, 256, SMEM_BYTES>>>(0, 1, 4, bias, nullptr);
    entangler_hybrid<true ><<<grid, 256, SMEM_BYTES>>>(1, 0, 5, bias, out);
}

// round 13
// speedup vs baseline: 1.7684x; 1.7684x over previous
#include <cuda_runtime.h>
#include <cuda_bf16.h>
#include <cstdint>

// ---------------- problem constants ----------------
#define MROWS 8192          // B*D = 256*32
#define KDIM  1024
#define NCOLS 1024
#define NSTEPS 6

// ---------------- scratch (__device__ globals; no allocation) ----------------
__device__ __nv_bfloat16 g_ah[2][MROWS * KDIM];      // activation hi, ping/pong
__device__ __nv_bfloat16 g_al[2][MROWS * KDIM];      // activation lo
__device__ __nv_bfloat16 g_wh[NSTEPS][KDIM * NCOLS]; // Wt hi: [n][k]
__device__ __nv_bfloat16 g_wl[NSTEPS][KDIM * NCOLS]; // Wt lo

// ---------------- GEMM tiling ----------------
#define BM 128
#define BN 128
#define BK 32                 // 2 x k16 per stage
#define NKT (KDIM / BK)       // 32
#define NSTAGE 2
#define NTHREADS 256

// smem per stage: A[hl=2][ks=2][128 rows][16 bf16 + 8 pad] then B same.
#define ROW_B   48
#define BLK_B   (128 * ROW_B)     // 6144
#define AREG_B  (4 * BLK_B)       // 24576
#define STAGE_B (2 * AREG_B)      // 49152
#define SMEM_BYTES (NSTAGE * STAGE_B)   // 98304 -> 2 CTAs/SM

__device__ __forceinline__ uint32_t s2u(const void* p) {
    uint32_t a;
    asm("{ .reg .u64 t; cvta.to.shared.u64 t, %1; cvt.u32.u64 %0, t; }" : "=r"(a) : "l"(p));
    return a;
}
__device__ __forceinline__ void ldm4(uint32_t* r, uint32_t a) {
    asm volatile("ldmatrix.sync.aligned.m8n8.x4.shared.b16 {%0,%1,%2,%3}, [%4];"
                 : "=r"(r[0]), "=r"(r[1]), "=r"(r[2]), "=r"(r[3]) : "r"(a));
}
__device__ __forceinline__ void mma_bf16(float* d, const uint32_t* a, const uint32_t* b) {
    asm volatile("mma.sync.aligned.m16n8k16.row.col.f32.bf16.bf16.f32 "
                 "{%0,%1,%2,%3}, {%4,%5,%6,%7}, {%8,%9}, {%0,%1,%2,%3};"
                 : "+f"(d[0]), "+f"(d[1]), "+f"(d[2]), "+f"(d[3])
                 : "r"(a[0]), "r"(a[1]), "r"(a[2]), "r"(a[3]), "r"(b[0]), "r"(b[1]));
}
__device__ __forceinline__ void split_bf16(float v, __nv_bfloat16& h, __nv_bfloat16& l) {
    h = __float2bfloat16(v);
    l = __float2bfloat16(v - __bfloat162float(h));
}

// ---------------- prep kernels ----------------
// A0[(b,f)][k=j*32+i] = X[b,i,j,f], split into hi/lo bf16.
__global__ void prep_x(const float* __restrict__ X) {
    __shared__ float t[32][33];
    const int b = blockIdx.x >> 5, j = blockIdx.x & 31;
    const int x = threadIdx.x, y = threadIdx.y;
    t[y][x] = X[b * 32768 + y * 1024 + j * 32 + x];   // y=i, x=f (coalesced)
    __syncthreads();
    const float v = t[x][y];                          // x=i, y=f
    __nv_bfloat16 h, l;
    split_bf16(v, h, l);
    const int addr = (b * 32 + y) * 1024 + j * 32 + x;
    g_ah[0][addr] = h;
    g_al[0][addr] = l;
}
// Wt[s][n][k] = W[s][(k&31)*32 + (k>>5)][n], split hi/lo.
__global__ void prep_w(const float* __restrict__ W) {
    __shared__ float t[32][33];
    const int s = blockIdx.z;
    const int k0 = blockIdx.x * 32, n0 = blockIdx.y * 32;
    const int x = threadIdx.x, y = threadIdx.y;
    const int kp = k0 + y;
    const int wrow = (kp & 31) * 32 + (kp >> 5);
    t[y][x] = W[s * 1048576 + wrow * 1024 + n0 + x];
    __syncthreads();
    const float v = t[x][y];
    __nv_bfloat16 h, l;
    split_bf16(v, h, l);
    const int addr = (n0 + y) * 1024 + k0 + x;
    g_wh[s][addr] = h;
    g_wl[s][addr] = l;
}

// ---------------- bf16x2 mma GEMM ----------------
// 256 threads, 8 warps (4m x 2n), warp tile 32x64. 2-stage pipeline, 2 CTAs/SM.
template <bool EPI>
__global__ __launch_bounds__(NTHREADS, 2)
void entangler_mma(int src, int dst, int s,
                   const float* __restrict__ bias, float* __restrict__ out) {
    extern __shared__ char smem[];
    const uint32_t smem_u = s2u(smem);

    const int tid  = threadIdx.x;
    const int wid  = tid >> 5;
    const int lane = tid & 31;
    const int col0 = blockIdx.x * BN;
    const int row0 = blockIdx.y * BM;
    const int warp_m = (wid & 3) * 32;
    const int warp_n = (wid >> 2) * 64;

    const __nv_bfloat16* __restrict__ Ahi = g_ah[src];
    const __nv_bfloat16* __restrict__ Alo = g_al[src];
    const __nv_bfloat16* __restrict__ Whi = g_wh[s];
    const __nv_bfloat16* __restrict__ Wlo = g_wl[s];
    __nv_bfloat16* __restrict__ Ahd = g_ah[dst];
    __nv_bfloat16* __restrict__ Ald = g_al[dst];

    float acc[2][8][4];
#pragma unroll
    for (int mt = 0; mt < 2; mt++)
#pragma unroll
        for (int nt = 0; nt < 8; nt++)
#pragma unroll
            for (int q = 0; q < 4; q++) acc[mt][nt][q] = 0.0f;

    // ---- cp.async staging ----
    auto issue = [&](int kt, int stg) {
        const uint32_t sbase = smem_u + stg * STAGE_B;
#pragma unroll
        for (int t = 0; t < 4; t++) {
            const int idx  = tid + t * NTHREADS;     // 0..1023
            const int m_l  = idx >> 3;               // 0..127
            const int sub  = idx & 7;
            const int hl   = sub >> 2;               // 0=hi 1=lo
            const int ch   = sub & 3;                // 16B chunk within 64B k-range
            const int ks   = ch >> 1;
            const int half = ch & 1;
            const uint32_t soff = ((hl * 2 + ks) * 128 + m_l) * ROW_B + half * 16;

            const __nv_bfloat16* ga =
                (hl ? Alo : Ahi) + (row0 + m_l) * 1024 + kt * 32 + ch * 8;
            asm volatile("cp.async.cg.shared.global [%0], [%1], 16;"
                         :: "r"(sbase + soff), "l"(ga));
            const __nv_bfloat16* gb =
                (hl ? Wlo : Whi) + (col0 + m_l) * 1024 + kt * 32 + ch * 8;
            asm volatile("cp.async.cg.shared.global [%0], [%1], 16;"
                         :: "r"(sbase + AREG_B + soff), "l"(gb));
        }
        asm volatile("cp.async.commit_group;" ::: "memory");
    };

    // ---- ldmatrix lane mappings (validated round 6) ----
    const int a_lr = (lane & 7) + ((lane >> 3) & 1) * 8;
    const int a_lb = (lane >> 4) * 16;
    const int b_nr = (lane >> 4) * 8 + (lane & 7);
    const int b_lb = ((lane >> 3) & 1) * 16;

    // compute restructured per-B-fragment to keep live regs ~110 (occupancy 2)
    auto compute = [&](int stg) {
        const uint32_t sbase = smem_u + stg * STAGE_B;
#pragma unroll
        for (int ks = 0; ks < 2; ks++) {
            uint32_t ah[2][4], al[2][4];
#pragma unroll
            for (int mt = 0; mt < 2; mt++) {
                const uint32_t ra = (warp_m + mt * 16 + a_lr) * ROW_B + a_lb;
                ldm4(ah[mt], sbase + (0 + ks) * BLK_B + ra);
                ldm4(al[mt], sbase + (2 + ks) * BLK_B + ra);
            }
#pragma unroll
            for (int ntp = 0; ntp < 4; ntp++) {
                const uint32_t rb = (warp_n + ntp * 16 + b_nr) * ROW_B + b_lb;
                uint32_t bh[4], bl[4];
                ldm4(bh, sbase + AREG_B + (0 + ks) * BLK_B + rb);
                ldm4(bl, sbase + AREG_B + (2 + ks) * BLK_B + rb);
                const int n0 = 2 * ntp;
                // 12 MMAs, same-acc dep distance 4
#pragma unroll
                for (int mt = 0; mt < 2; mt++) {
                    mma_bf16(acc[mt][n0],     ah[mt], bh);
                    mma_bf16(acc[mt][n0 + 1], ah[mt], bh + 2);
                }
#pragma unroll
                for (int mt = 0; mt < 2; mt++) {
                    mma_bf16(acc[mt][n0],     ah[mt], bl);
                    mma_bf16(acc[mt][n0 + 1], ah[mt], bl + 2);
                }
#pragma unroll
                for (int mt = 0; mt < 2; mt++) {
                    mma_bf16(acc[mt][n0],     al[mt], bh);
                    mma_bf16(acc[mt][n0 + 1], al[mt], bh + 2);
                }
            }
        }
    };

    // ---- 2-stage pipeline, double-sync (2nd CTA on the SM hides bubbles) ----
    issue(0, 0);
#pragma unroll 1
    for (int kt = 0; kt < NKT; kt++) {
        if (kt + 1 < NKT) {
            issue(kt + 1, (kt + 1) & 1);
            asm volatile("cp.async.wait_group 1;" ::: "memory");
        } else {
            asm volatile("cp.async.wait_group 0;" ::: "memory");
        }
        __syncthreads();
        compute(kt & 1);
        if (kt + 1 < NKT) __syncthreads();
    }

    // ---- epilogue ----
    const int lrow = lane >> 2;
    const int lcol = (lane & 3) * 2;
#pragma unroll
    for (int mt = 0; mt < 2; mt++) {
#pragma unroll
        for (int nt = 0; nt < 8; nt++) {
            const int gr0 = row0 + warp_m + mt * 16 + lrow;
            const int gn  = col0 + warp_n + nt * 8 + lcol;
#pragma unroll
            for (int half = 0; half < 2; half++) {
                const int r = gr0 + half * 8;
                float v0 = acc[mt][nt][half * 2 + 0];
                float v1 = acc[mt][nt][half * 2 + 1];
                if (EPI) {
                    const int f = r & 31;
                    v0 = fmaxf(v0 + bias[f * 1024 + gn], 0.0f);
                    v1 = fmaxf(v1 + bias[f * 1024 + gn + 1], 0.0f);
                    *(float2*)(out + r * 1024 + gn) = make_float2(v0, v1);
                } else {
                    // scatter into next step's row-major A layout
                    const int b = r >> 5, f = r & 31;
                    const int addr = (b * 32 + (gn >> 5)) * 1024 + f * 32 + (gn & 31);
                    __nv_bfloat16 h0, l0, h1, l1;
                    split_bf16(v0, h0, l0);
                    split_bf16(v1, h1, l1);
                    __nv_bfloat162 hp; hp.x = h0; hp.y = h1;
                    __nv_bfloat162 lp; lp.x = l0; lp.y = l1;
                    *(__nv_bfloat162*)(&Ahd[addr]) = hp;
                    *(__nv_bfloat162*)(&Ald[addr]) = lp;
                }
            }
        }
    }
}

// ---------------- launch ----------------
extern "C" void kernel_launch(void* const* d_in, const int* in_sizes, int n_in,
                              void* d_out, int out_size) {
    const float* X     = (const float*)d_in[0];
    const float* nodes = (const float*)d_in[1];
    const float* bias  = (const float*)d_in[2];
    float* out = (float*)d_out;

    cudaFuncSetAttribute(entangler_mma<false>,
                         cudaFuncAttributeMaxDynamicSharedMemorySize, SMEM_BYTES);
    cudaFuncSetAttribute(entangler_mma<true>,
                         cudaFuncAttributeMaxDynamicSharedMemorySize, SMEM_BYTES);

    prep_x<<<MROWS, dim3(32, 32)>>>(X);
    prep_w<<<dim3(32, 32, NSTEPS), dim3(32, 32)>>>(nodes);

    dim3 grid(NCOLS / BN, MROWS / BM);   // (8, 64) = 512 CTAs
    entangler_mma<false><<<grid, NTHREADS, SMEM_BYTES>>>(0, 1, 0, bias, nullptr);
    entangler_mma<false><<<grid, NTHREADS, SMEM_BYTES>>>(1, 0, 1, bias, nullptr);
    entangler_mma<false><<<grid, NTHREADS, SMEM_BYTES>>>(0, 1, 2, bias, nullptr);
    entangler_mma<false><<<grid, NTHREADS, SMEM_BYTES>>>(1, 0, 3, bias, nullptr);
    entangler_mma<false><<<grid, NTHREADS, SMEM_BYTES>>>(0, 1, 4, bias, nullptr);
    entangler_mma<true ><<<grid, NTHREADS, SMEM_BYTES>>>(1, 0, 5, bias, out);
}